// round 9
// baseline (speedup 1.0000x reference)
#include <cuda_runtime.h>

#define NI 16384          // inputs per batch row
#define ND 65536          // detectors
#define KK 32             // members per detector (== warp size)
#define BB 32             // batch
#define NCHUNK 32         // detector tiles
#define DET_PER_CTA (ND / NCHUNK)   // 2048
#define THREADS 1024
#define WARPS (THREADS / 32)        // 32
#define DET_PER_WARP (DET_PER_CTA / WARPS)  // 64
#define SMEM_BYTES (NI * 4)         // 64KB: packed {key16_A, key16_B}

// Global scratch (allocation-free rule: __device__ globals).
// spike(b,i) <=> wins(b,i) == memberships(i): each detector contributes one
// winner slot and K-1 loser slots, so stat = M - W. Duplicate ids / exact
// value ties preserved (winner = lowest max slot). rel_err 0.0 in R6-R8.
__device__ unsigned g_M[NI];
__device__ unsigned g_W[BB * NI];

__global__ void zero_kernel() {
    int i = blockIdx.x * blockDim.x + threadIdx.x;   // covers (BB+1)*NI
    if (i < NI) g_M[i] = 0u;
    else        g_W[i - NI] = 0u;
}

// M histogram: one fire-and-forget RED.ADD per (detector, slot) entry.
__global__ void count_kernel(const int* __restrict__ det) {
    int idx = blockIdx.x * blockDim.x + threadIdx.x;   // [0, ND*KK)
    atomicAdd(&g_M[__ldg(det + idx)], 1u);             // REDG
}

// Order-preserving float -> unsigned key: x >= y (as floats) iff
// key(x) >= key(y) as unsigned. Equal floats -> equal keys.
// Finite floats map to keys in (0, 0xFFFFFFFF), so 0 is a safe sentinel.
__device__ __forceinline__ unsigned f32_order_key(unsigned u) {
    return u ^ (((int)u >> 31) | 0x80000000u);
}

// One CTA = one detector tile x one batch pair. smem holds a 16-bit
// truncated order key per (input, batch): monotone, so a UNIQUE warp-max
// key16 identifies the exact winner. Ties on key16 (warp-uniform, ~5%)
// fall back to exact fp32 keys reloaded from L2.
__global__ void __launch_bounds__(THREADS, 2) winner_kernel(
    const float* __restrict__ x,
    const int*   __restrict__ det)
{
    extern __shared__ unsigned keys[];           // 64KB

    const int tid   = threadIdx.x;
    const int chunk = blockIdx.x;               // 0..NCHUNK-1
    const int b0    = blockIdx.y * 2;           // batch pair base

    const float* rowA = x + (size_t)b0 * NI;
    const float* rowB = rowA + NI;

    // Prologue: build packed key16 pairs (coalesced loads).
    #pragma unroll
    for (int i = tid; i < NI; i += THREADS) {
        unsigned ka = f32_order_key(__float_as_uint(__ldg(rowA + i)));
        unsigned kb = f32_order_key(__float_as_uint(__ldg(rowB + i)));
        keys[i] = (ka & 0xFFFF0000u) | (kb >> 16);
    }
    __syncthreads();

    const int lane = tid & 31;
    const int warp = tid >> 5;
    unsigned* WA = g_W + (size_t)b0 * NI;
    unsigned* WB = WA + NI;

    // Warp w owns DET_PER_WARP consecutive detectors; one detector row
    // == 128B == exactly one coalesced warp load.
    const int* dbase = det
        + ((size_t)(chunk * DET_PER_CTA + warp * DET_PER_WARP)) * KK + lane;

    #pragma unroll 4
    for (int i = 0; i < DET_PER_WARP; i++) {
        int id = __ldg(dbase + i * KK);
        unsigned p = keys[id];                     // LDS.32: both batches
        unsigned kA = p >> 16;
        unsigned kB = p & 0xFFFFu;

        // --- batch A ---
        unsigned mA = __reduce_max_sync(0xffffffffu, kA);
        unsigned balA = __ballot_sync(0xffffffffu, kA == mA);
        if (__popc(balA) > 1) {                    // warp-uniform, rare
            bool cand = (balA >> lane) & 1u;
            unsigned ek = 0u;
            if (cand) ek = f32_order_key(__float_as_uint(__ldg(rowA + id)));
            unsigned mE = __reduce_max_sync(0xffffffffu, ek);
            balA = __ballot_sync(0xffffffffu, cand && ek == mE);
        }
        // winner = lowest max lane (jnp.argmax tie-break); fire REDG.
        if (lane == __ffs(balA) - 1)
            atomicAdd(WA + id, 1u);

        // --- batch B ---
        unsigned mB = __reduce_max_sync(0xffffffffu, kB);
        unsigned balB = __ballot_sync(0xffffffffu, kB == mB);
        if (__popc(balB) > 1) {
            bool cand = (balB >> lane) & 1u;
            unsigned ek = 0u;
            if (cand) ek = f32_order_key(__float_as_uint(__ldg(rowB + id)));
            unsigned mE = __reduce_max_sync(0xffffffffu, ek);
            balB = __ballot_sync(0xffffffffu, cand && ek == mE);
        }
        if (lane == __ffs(balB) - 1)
            atomicAdd(WB + id, 1u);
    }
}

__global__ void finalize_kernel(float* __restrict__ out) {
    int idx = blockIdx.x * blockDim.x + threadIdx.x;   // [0, BB*NI)
    out[idx] = (g_W[idx] == g_M[idx & (NI - 1)]) ? 1.0f : 0.0f;
}

extern "C" void kernel_launch(void* const* d_in, const int* in_sizes, int n_in,
                              void* d_out, int out_size) {
    const float* x   = (const float*)d_in[0];   // [32, 16384] f32
    const int*   det = (const int*)d_in[1];     // [65536, 32] i32
    float*       out = (float*)d_out;           // [32, 16384] f32

    (void)in_sizes; (void)n_in; (void)out_size;

    cudaFuncSetAttribute(winner_kernel,
                         cudaFuncAttributeMaxDynamicSharedMemorySize,
                         SMEM_BYTES);

    // 1) Zero M and W counters.
    zero_kernel<<<((BB + 1) * NI + 511) / 512, 512>>>();
    // 2) Membership histogram (batch-independent, rebuilt every call).
    count_kernel<<<(ND * KK) / 512, 512>>>(det);
    // 3) Winner counting: detector tile x batch pair, 64 warps/SM.
    dim3 grid(NCHUNK, BB / 2);
    winner_kernel<<<grid, THREADS, SMEM_BYTES>>>(x, det);
    // 4) spike = (wins == memberships).
    finalize_kernel<<<(BB * NI) / 512, 512>>>(out);
}

// round 10
// speedup vs baseline: 1.0010x; 1.0010x over previous
#include <cuda_runtime.h>

#define NI 16384          // inputs per batch row
#define ND 65536          // detectors
#define KK 32             // members per detector (== warp size)
#define BB 32             // batch
#define NCHUNK 16         // detector tiles
#define DET_PER_CTA (ND / NCHUNK)   // 4096
#define THREADS 1024
#define WARPS (THREADS / 32)        // 32
#define DET_PER_WARP (DET_PER_CTA / WARPS)  // 128
#define SMEM_BYTES (NI * 8)         // 128KB: uint2 {keyA, keyB} per input

// Global scratch (allocation-free rule: __device__ globals; zero-initialized
// at module load). spike(b,i) <=> wins(b,i) == memberships(i): each detector
// contributes 1 winner slot + K-1 loser slots, so stat = M - W. Duplicate ids
// and exact value ties preserved (winner = lowest max slot), matching
// jnp.argmax. rel_err 0.0 across R6-R9.
// Invariant: g_W == 0 and g_M == 0 at kernel_launch entry (finalize resets W,
// reset_M resets M each call; statics start zeroed).
__device__ unsigned g_M[NI];
__device__ unsigned g_W[BB * NI];

__global__ void reset_m_kernel() {
    g_M[blockIdx.x * blockDim.x + threadIdx.x] = 0u;
}

// Order-preserving float -> unsigned key: x >= y (as floats) iff
// key(x) >= key(y) as unsigned. Equal floats -> equal keys.
__device__ __forceinline__ unsigned f32_order_key(unsigned u) {
    return u ^ (((int)u >> 31) | 0x80000000u);
}

// One CTA = one detector tile x one batch pair. One LDS.64 gather serves
// both batches; winner lane fires one gmem RED.ADD per (detector, batch).
// pair==0 CTAs additionally build the membership histogram g_M from the
// same det stream (they're the only CTAs whose chunk+pair covers each det
// row exactly once across blockIdx.y==0).
__global__ void __launch_bounds__(THREADS, 1) winner_kernel(
    const float* __restrict__ x,
    const int*   __restrict__ det)
{
    extern __shared__ uint2 xs2[];               // 128KB: {keyA, keyB}

    const int tid   = threadIdx.x;
    const int chunk = blockIdx.x;               // 0..NCHUNK-1
    const int b0    = blockIdx.y * 2;           // batch pair base
    const bool do_count = (blockIdx.y == 0);

    // Prologue: precompute order keys for both rows (coalesced loads).
    const float* rowA = x + (size_t)b0 * NI;
    const float* rowB = rowA + NI;
    #pragma unroll
    for (int i = tid; i < NI; i += THREADS) {
        unsigned ka = f32_order_key(__float_as_uint(__ldg(rowA + i)));
        unsigned kb = f32_order_key(__float_as_uint(__ldg(rowB + i)));
        xs2[i] = make_uint2(ka, kb);
    }
    __syncthreads();

    const int lane = tid & 31;
    const int warp = tid >> 5;
    const unsigned lt_mask = (1u << lane) - 1u;
    unsigned* WA = g_W + (size_t)b0 * NI;
    unsigned* WB = WA + NI;

    // Warp w owns DET_PER_WARP consecutive detectors; one detector row
    // == 128B == exactly one coalesced warp load.
    const int* dbase = det
        + ((size_t)(chunk * DET_PER_CTA + warp * DET_PER_WARP)) * KK + lane;

    if (do_count) {
        #pragma unroll 8
        for (int i = 0; i < DET_PER_WARP; i++) {
            int id = __ldg(dbase + i * KK);
            atomicAdd(&g_M[id], 1u);                 // REDG, fire-and-forget
            uint2 p = xs2[id];                       // LDS.64: both batches
            unsigned mA = __reduce_max_sync(0xffffffffu, p.x);
            unsigned mB = __reduce_max_sync(0xffffffffu, p.y);
            unsigned balA = __ballot_sync(0xffffffffu, p.x == mA);
            unsigned balB = __ballot_sync(0xffffffffu, p.y == mB);
            if (p.x == mA && (balA & lt_mask) == 0u) atomicAdd(WA + id, 1u);
            if (p.y == mB && (balB & lt_mask) == 0u) atomicAdd(WB + id, 1u);
        }
    } else {
        #pragma unroll 8
        for (int i = 0; i < DET_PER_WARP; i++) {
            int id = __ldg(dbase + i * KK);
            uint2 p = xs2[id];
            unsigned mA = __reduce_max_sync(0xffffffffu, p.x);
            unsigned mB = __reduce_max_sync(0xffffffffu, p.y);
            unsigned balA = __ballot_sync(0xffffffffu, p.x == mA);
            unsigned balB = __ballot_sync(0xffffffffu, p.y == mB);
            if (p.x == mA && (balA & lt_mask) == 0u) atomicAdd(WA + id, 1u);
            if (p.y == mB && (balB & lt_mask) == 0u) atomicAdd(WB + id, 1u);
        }
    }
}

// Writes the output AND resets g_W for the next replay (own-address reset:
// race-free). g_M is reset by reset_m_kernel at the start of the next call
// (it is read 32x per word here, so it cannot be reset in this kernel).
__global__ void finalize_kernel(float* __restrict__ out) {
    int idx = blockIdx.x * blockDim.x + threadIdx.x;   // [0, BB*NI)
    unsigned w = g_W[idx];
    out[idx] = (w == g_M[idx & (NI - 1)]) ? 1.0f : 0.0f;
    g_W[idx] = 0u;
}

extern "C" void kernel_launch(void* const* d_in, const int* in_sizes, int n_in,
                              void* d_out, int out_size) {
    const float* x   = (const float*)d_in[0];   // [32, 16384] f32
    const int*   det = (const int*)d_in[1];     // [65536, 32] i32
    float*       out = (float*)d_out;           // [32, 16384] f32

    (void)in_sizes; (void)n_in; (void)out_size;

    cudaFuncSetAttribute(winner_kernel,
                         cudaFuncAttributeMaxDynamicSharedMemorySize,
                         SMEM_BYTES);

    // 1) Reset M (W was reset by the previous finalize / static init).
    reset_m_kernel<<<NI / 512, 512>>>();
    // 2) Winner counting (+ embedded membership histogram on pair==0).
    dim3 grid(NCHUNK, BB / 2);
    winner_kernel<<<grid, THREADS, SMEM_BYTES>>>(x, det);
    // 3) spike = (wins == memberships); self-resets W.
    finalize_kernel<<<(BB * NI) / 512, 512>>>(out);
}

// round 11
// speedup vs baseline: 1.3231x; 1.3218x over previous
#include <cuda_runtime.h>

#define NI 16384          // inputs per batch row
#define ND 65536          // detectors
#define KK 32             // members per detector (== warp size)
#define BB 32             // batch
#define NCHUNK 32         // detector tiles
#define DET_PER_CTA (ND / NCHUNK)   // 2048
#define THREADS 1024
#define WARPS (THREADS / 32)        // 32
#define DET_PER_WARP (DET_PER_CTA / WARPS)  // 64
#define SMEM_BYTES (NI * 8)         // 128KB: uint2 {keyA, keyB} per input
#define NPAIR (BB / 2)              // 16

// Global scratch (allocation-free rule; zero-initialized at module load).
// spike(b,i) <=> wins(b,i) == memberships(i): each detector contributes one
// winner slot + K-1 loser slots, so stat = M - W. Duplicate ids and exact
// value ties preserved (winner = lowest max slot), matching jnp.argmax.
// rel_err 0.0 across R6-R10 with this identity.
// Invariant at kernel_launch entry: g_M == 0 and g_W == 0 (finalize resets
// both; statics start zeroed), so the launch is replay-deterministic.
__device__ unsigned g_M[NI];
__device__ unsigned g_W[BB * NI];

// Order-preserving float -> unsigned key: x >= y (as floats) iff
// key(x) >= key(y) as unsigned. Equal floats -> equal keys.
__device__ __forceinline__ unsigned f32_order_key(unsigned u) {
    return u ^ (((int)u >> 31) | 0x80000000u);
}

// One CTA = one detector tile x one batch pair. One LDS.64 gather serves
// both batches; the winner lane fires a fire-and-forget gmem RED.ADD.
// Membership histogram is built inline: each CTA counts the det rows with
// (i & 15) == pair, so every row is counted exactly once across the grid
// and the extra REDG cost is evenly spread (+1/16 of iters per CTA).
// Software-pipelined: iter i+1's det load + smem gather issue before the
// reduction of iter i, keeping >=2 iterations in flight per warp.
__global__ void __launch_bounds__(THREADS, 1) winner_kernel(
    const float* __restrict__ x,
    const int*   __restrict__ det)
{
    extern __shared__ uint2 xs2[];               // 128KB: {keyA, keyB}

    const int tid   = threadIdx.x;
    const int chunk = blockIdx.x;               // 0..NCHUNK-1
    const int pair  = blockIdx.y;               // 0..NPAIR-1
    const int b0    = pair * 2;

    // Prologue: precompute order keys for both rows (coalesced loads).
    const float* rowA = x + (size_t)b0 * NI;
    const float* rowB = rowA + NI;
    #pragma unroll
    for (int i = tid; i < NI; i += THREADS) {
        unsigned ka = f32_order_key(__float_as_uint(__ldg(rowA + i)));
        unsigned kb = f32_order_key(__float_as_uint(__ldg(rowB + i)));
        xs2[i] = make_uint2(ka, kb);
    }
    __syncthreads();

    const int lane = tid & 31;
    const int warp = tid >> 5;
    const unsigned lt_mask = (1u << lane) - 1u;
    unsigned* WA = g_W + (size_t)b0 * NI;
    unsigned* WB = WA + NI;

    // Warp w owns DET_PER_WARP consecutive detectors; one detector row
    // == 128B == exactly one coalesced warp load.
    const int* dbase = det
        + ((size_t)(chunk * DET_PER_CTA + warp * DET_PER_WARP)) * KK + lane;

    // Pipeline prime: iter 0's id + gather.
    int   id_cur = __ldg(dbase);
    uint2 p_cur  = xs2[id_cur];

    #pragma unroll 4
    for (int i = 0; i < DET_PER_WARP; i++) {
        // Prefetch next iteration's id and gather before reducing this one.
        int   id_nxt = 0;
        uint2 p_nxt  = make_uint2(0u, 0u);
        if (i + 1 < DET_PER_WARP) {
            id_nxt = __ldg(dbase + (i + 1) * KK);
            p_nxt  = xs2[id_nxt];
        }

        // Inline membership histogram (exactly-once across pair groups).
        if ((i & (NPAIR - 1)) == pair)
            atomicAdd(&g_M[id_cur], 1u);             // spread REDG

        unsigned mA = __reduce_max_sync(0xffffffffu, p_cur.x);
        unsigned mB = __reduce_max_sync(0xffffffffu, p_cur.y);
        unsigned balA = __ballot_sync(0xffffffffu, p_cur.x == mA);
        unsigned balB = __ballot_sync(0xffffffffu, p_cur.y == mB);
        // winner = lowest lane achieving max (jnp.argmax tie-break);
        // one fire-and-forget gmem RED.ADD from that lane.
        if (p_cur.x == mA && (balA & lt_mask) == 0u) atomicAdd(WA + id_cur, 1u);
        if (p_cur.y == mB && (balB & lt_mask) == 0u) atomicAdd(WB + id_cur, 1u);

        id_cur = id_nxt;
        p_cur  = p_nxt;
    }
}

// Column-tiled finalize: block j owns input columns [j*512, (j+1)*512).
// Reads each g_M word once, emits coalesced output rows for all 32 batches,
// and resets BOTH g_W and g_M (own-address writes after all reads -> safe,
// since only this block touches these columns). Replaces three kernels.
__global__ void __launch_bounds__(512, 4) finalize_kernel(float* __restrict__ out) {
    const int col = blockIdx.x * 512 + threadIdx.x;   // grid = NI/512 blocks
    const unsigned m = g_M[col];
    #pragma unroll 4
    for (int b = 0; b < BB; b++) {
        const int idx = b * NI + col;
        out[idx] = (g_W[idx] == m) ? 1.0f : 0.0f;
        g_W[idx] = 0u;
    }
    g_M[col] = 0u;
}

extern "C" void kernel_launch(void* const* d_in, const int* in_sizes, int n_in,
                              void* d_out, int out_size) {
    const float* x   = (const float*)d_in[0];   // [32, 16384] f32
    const int*   det = (const int*)d_in[1];     // [65536, 32] i32
    float*       out = (float*)d_out;           // [32, 16384] f32

    (void)in_sizes; (void)n_in; (void)out_size;

    cudaFuncSetAttribute(winner_kernel,
                         cudaFuncAttributeMaxDynamicSharedMemorySize,
                         SMEM_BYTES);

    // 1) Winner counting + inline membership histogram (needs M=W=0, which
    //    the previous finalize / static zero-init guarantees).
    dim3 grid(NCHUNK, NPAIR);
    winner_kernel<<<grid, THREADS, SMEM_BYTES>>>(x, det);
    // 2) spike = (wins == memberships); resets W and M for the next call.
    finalize_kernel<<<NI / 512, 512>>>(out);
}

// round 12
// speedup vs baseline: 1.4836x; 1.1213x over previous
#include <cuda_runtime.h>

#define NI 16384          // inputs per batch row
#define ND 65536          // detectors
#define KK 32             // members per detector (== warp size)
#define BB 32             // batch
#define NCHUNK 32         // detector tiles
#define DET_PER_CTA (ND / NCHUNK)   // 2048
#define THREADS 1024
#define WARPS (THREADS / 32)        // 32
#define DET_PER_WARP (DET_PER_CTA / WARPS)  // 64
#define SMEM_BYTES (NI * 8)         // 128KB: uint2 {keyA, keyB} per input
#define NPAIR (BB / 2)              // 16

// Global scratch (allocation-free rule; zero-initialized at module load).
// spike(b,i) <=> wins(b,i) == memberships(i): each detector contributes one
// winner slot + K-1 loser slots, so stat = M - W. Duplicate ids and exact
// value ties preserved (winner = lowest max slot), matching jnp.argmax.
// rel_err 0.0 across R6-R11 with this identity.
// Invariant at kernel_launch entry: g_M == 0 and g_W == 0 (finalize resets
// both; statics start zeroed), so the launch is replay-deterministic.
__device__ unsigned g_M[NI];
__device__ unsigned g_W[BB * NI];

// Order-preserving float -> unsigned key: x >= y (as floats) iff
// key(x) >= key(y) as unsigned. Equal floats -> equal keys.
__device__ __forceinline__ unsigned f32_order_key(unsigned u) {
    return u ^ (((int)u >> 31) | 0x80000000u);
}

// One CTA = one detector tile x one batch pair. One LDS.64 gather serves
// both batches; the winner lane fires a fire-and-forget gmem RED.ADD.
// Membership histogram built inline: each CTA counts det rows with
// (i & 15) == pair -> every row counted exactly once across the grid.
// Depth-2 software pipeline: det ids are prefetched TWO iterations ahead
// (LDG), gathers ONE ahead (LDS), so the LDS never issues back-to-back
// with its producing LDG and the reduce never waits on a fresh LDS.
__global__ void __launch_bounds__(THREADS, 1) winner_kernel(
    const float* __restrict__ x,
    const int*   __restrict__ det)
{
    extern __shared__ uint2 xs2[];               // 128KB: {keyA, keyB}

    const int tid   = threadIdx.x;
    const int chunk = blockIdx.x;               // 0..NCHUNK-1
    const int pair  = blockIdx.y;               // 0..NPAIR-1
    const int b0    = pair * 2;

    // Prologue: precompute order keys for both rows (coalesced loads).
    const float* rowA = x + (size_t)b0 * NI;
    const float* rowB = rowA + NI;
    #pragma unroll
    for (int i = tid; i < NI; i += THREADS) {
        unsigned ka = f32_order_key(__float_as_uint(__ldg(rowA + i)));
        unsigned kb = f32_order_key(__float_as_uint(__ldg(rowB + i)));
        xs2[i] = make_uint2(ka, kb);
    }
    __syncthreads();

    const int lane = tid & 31;
    const int warp = tid >> 5;
    const unsigned lt_mask = (1u << lane) - 1u;
    unsigned* WA = g_W + (size_t)b0 * NI;
    unsigned* WB = WA + NI;

    // Warp w owns DET_PER_WARP consecutive detectors; one detector row
    // == 128B == exactly one coalesced warp load.
    const int* dbase = det
        + ((size_t)(chunk * DET_PER_CTA + warp * DET_PER_WARP)) * KK + lane;

    // Pipeline prime: ids for iters 0 and 1, gather for iter 0.
    int   id_c = __ldg(dbase);                   // iter 0 id
    int   id_n = __ldg(dbase + KK);              // iter 1 id
    uint2 p_c  = xs2[id_c];                      // iter 0 gather

    #pragma unroll 4
    for (int i = 0; i < DET_PER_WARP; i++) {
        // Prefetch: id two ahead (LDG), gather one ahead (LDS on an id
        // loaded a full iteration ago -> L2 latency already absorbed).
        int id_f = 0;
        if (i + 2 < DET_PER_WARP) id_f = __ldg(dbase + (i + 2) * KK);
        uint2 p_n = make_uint2(0u, 0u);
        if (i + 1 < DET_PER_WARP) p_n = xs2[id_n];

        // Inline membership histogram (exactly-once across pair groups).
        if ((i & (NPAIR - 1)) == pair)
            atomicAdd(&g_M[id_c], 1u);           // spread REDG

        unsigned mA = __reduce_max_sync(0xffffffffu, p_c.x);
        unsigned mB = __reduce_max_sync(0xffffffffu, p_c.y);
        unsigned balA = __ballot_sync(0xffffffffu, p_c.x == mA);
        unsigned balB = __ballot_sync(0xffffffffu, p_c.y == mB);
        // winner = lowest lane achieving max (jnp.argmax tie-break);
        // one fire-and-forget gmem RED.ADD from that lane.
        if (p_c.x == mA && (balA & lt_mask) == 0u) atomicAdd(WA + id_c, 1u);
        if (p_c.y == mB && (balB & lt_mask) == 0u) atomicAdd(WB + id_c, 1u);

        id_c = id_n; id_n = id_f; p_c = p_n;
    }
}

// Finalize: 128 blocks x 512 threads. Block j owns columns
// [j*128, (j+1)*128); threads = 4 batch-slices x 128 columns (consecutive
// tids -> consecutive columns -> fully coalesced W/out rows). Each g_M word
// is read only inside its owning block, so after __syncthreads() the block
// safely resets it. Resets g_W inline (own-address). Two-launch total.
__global__ void __launch_bounds__(512) finalize_kernel(float* __restrict__ out) {
    const int col = blockIdx.x * 128 + (threadIdx.x & 127);
    const int bs  = (threadIdx.x >> 7) * (BB / 4);   // 0, 8, 16, 24
    const unsigned m = g_M[col];
    #pragma unroll
    for (int b = bs; b < bs + BB / 4; b++) {
        const int idx = b * NI + col;
        out[idx] = (g_W[idx] == m) ? 1.0f : 0.0f;
        g_W[idx] = 0u;
    }
    __syncthreads();
    if (threadIdx.x < 128)
        g_M[blockIdx.x * 128 + threadIdx.x] = 0u;
}

extern "C" void kernel_launch(void* const* d_in, const int* in_sizes, int n_in,
                              void* d_out, int out_size) {
    const float* x   = (const float*)d_in[0];   // [32, 16384] f32
    const int*   det = (const int*)d_in[1];     // [65536, 32] i32
    float*       out = (float*)d_out;           // [32, 16384] f32

    (void)in_sizes; (void)n_in; (void)out_size;

    cudaFuncSetAttribute(winner_kernel,
                         cudaFuncAttributeMaxDynamicSharedMemorySize,
                         SMEM_BYTES);

    // 1) Winner counting + inline membership histogram (needs M=W=0,
    //    guaranteed by the previous finalize / static zero-init).
    dim3 grid(NCHUNK, NPAIR);
    winner_kernel<<<grid, THREADS, SMEM_BYTES>>>(x, det);
    // 2) spike = (wins == memberships); resets W and M for the next call.
    finalize_kernel<<<NI / 128, 512>>>(out);
}

// round 13
// speedup vs baseline: 1.4982x; 1.0098x over previous
#include <cuda_runtime.h>

#define NI 16384          // inputs per batch row
#define ND 65536          // detectors
#define KK 32             // members per detector (== warp size)
#define BB 32             // batch
#define NCHUNK 32         // detector tiles
#define DET_PER_CTA (ND / NCHUNK)   // 2048
#define THREADS 1024
#define WARPS (THREADS / 32)        // 32
#define DET_PER_WARP (DET_PER_CTA / WARPS)  // 64
#define HALF (DET_PER_WARP / 2)     // 32: per-stream iterations
#define SMEM_BYTES (NI * 8)         // 128KB: uint2 {keyA, keyB} per input
#define NPAIR (BB / 2)              // 16

// Global scratch (allocation-free rule; zero-initialized at module load).
// spike(b,i) <=> wins(b,i) == memberships(i): each detector contributes one
// winner slot + K-1 loser slots, so stat = M - W. Duplicate ids and exact
// value ties preserved (winner = lowest max slot), matching jnp.argmax.
// rel_err 0.0 across R6-R12 with this identity.
// Invariant at kernel_launch entry: g_M == 0 and g_W == 0 (finalize resets
// both; statics start zeroed), so the launch is replay-deterministic.
__device__ unsigned g_M[NI];
__device__ unsigned g_W[BB * NI];

// Order-preserving float -> unsigned key: x >= y (as floats) iff
// key(x) >= key(y) as unsigned. Equal floats -> equal keys.
__device__ __forceinline__ unsigned f32_order_key(unsigned u) {
    return u ^ (((int)u >> 31) | 0x80000000u);
}

// One CTA = one detector tile x one batch pair. Each warp runs TWO
// independent detector streams per iteration (rows i and i+32 of its 64),
// so every iteration carries 2 LDG + 2 LDS.64 + 4 reduce chains of
// independent work -> latency overlap without deep pipelining.
// Membership histogram built inline: stream rows are counted when
// (i & 15) == pair, exactly once per row across the 16 pair-groups.
__global__ void __launch_bounds__(THREADS, 1) winner_kernel(
    const float* __restrict__ x,
    const int*   __restrict__ det)
{
    extern __shared__ uint2 xs2[];               // 128KB: {keyA, keyB}

    const int tid   = threadIdx.x;
    const int chunk = blockIdx.x;               // 0..NCHUNK-1
    const int pair  = blockIdx.y;               // 0..NPAIR-1
    const int b0    = pair * 2;

    // Prologue: precompute order keys for both rows (coalesced loads).
    const float* rowA = x + (size_t)b0 * NI;
    const float* rowB = rowA + NI;
    #pragma unroll
    for (int i = tid; i < NI; i += THREADS) {
        unsigned ka = f32_order_key(__float_as_uint(__ldg(rowA + i)));
        unsigned kb = f32_order_key(__float_as_uint(__ldg(rowB + i)));
        xs2[i] = make_uint2(ka, kb);
    }
    __syncthreads();

    const int lane = tid & 31;
    const int warp = tid >> 5;
    const unsigned lt_mask = (1u << lane) - 1u;
    unsigned* WA = g_W + (size_t)b0 * NI;
    unsigned* WB = WA + NI;

    // Warp w owns DET_PER_WARP consecutive detector rows; one row == 128B
    // == one coalesced warp load. Stream 0: rows [0,32); stream 1: [32,64).
    const int* dbase = det
        + ((size_t)(chunk * DET_PER_CTA + warp * DET_PER_WARP)) * KK + lane;
    const int* dbase1 = dbase + HALF * KK;

    // Prime both streams (iteration 0 ids + gathers).
    int   id0 = __ldg(dbase);
    int   id1 = __ldg(dbase1);
    uint2 p0  = xs2[id0];
    uint2 p1  = xs2[id1];

    #pragma unroll 4
    for (int i = 0; i < HALF; i++) {
        // Prefetch next iteration's ids and gathers (both streams).
        int id0n = 0, id1n = 0;
        uint2 p0n = make_uint2(0u, 0u), p1n = make_uint2(0u, 0u);
        if (i + 1 < HALF) {
            id0n = __ldg(dbase  + (i + 1) * KK);
            id1n = __ldg(dbase1 + (i + 1) * KK);
            p0n  = xs2[id0n];
            p1n  = xs2[id1n];
        }

        // Inline membership histogram (each det row exactly once).
        if ((i & (NPAIR - 1)) == pair) {
            atomicAdd(&g_M[id0], 1u);            // spread REDG
            atomicAdd(&g_M[id1], 1u);
        }

        unsigned m0A = __reduce_max_sync(0xffffffffu, p0.x);
        unsigned m0B = __reduce_max_sync(0xffffffffu, p0.y);
        unsigned m1A = __reduce_max_sync(0xffffffffu, p1.x);
        unsigned m1B = __reduce_max_sync(0xffffffffu, p1.y);
        unsigned b0A = __ballot_sync(0xffffffffu, p0.x == m0A);
        unsigned b0B = __ballot_sync(0xffffffffu, p0.y == m0B);
        unsigned b1A = __ballot_sync(0xffffffffu, p1.x == m1A);
        unsigned b1B = __ballot_sync(0xffffffffu, p1.y == m1B);
        // winner = lowest lane achieving max (jnp.argmax tie-break);
        // one fire-and-forget gmem RED.ADD per (detector, batch).
        if (p0.x == m0A && (b0A & lt_mask) == 0u) atomicAdd(WA + id0, 1u);
        if (p0.y == m0B && (b0B & lt_mask) == 0u) atomicAdd(WB + id0, 1u);
        if (p1.x == m1A && (b1A & lt_mask) == 0u) atomicAdd(WA + id1, 1u);
        if (p1.y == m1B && (b1B & lt_mask) == 0u) atomicAdd(WB + id1, 1u);

        id0 = id0n; id1 = id1n; p0 = p0n; p1 = p1n;
    }
}

// Finalize: 1024 blocks x 512 threads; block j owns 16 columns
// [j*16, (j+1)*16) for ALL 32 batches (one element per thread).
// Consecutive tids -> consecutive columns (coalesced within 64B segments).
// g_M[col] is read only inside its owning block, so after __syncthreads()
// the block resets it. g_W reset inline (own address). Two-launch total.
__global__ void __launch_bounds__(512) finalize_kernel(float* __restrict__ out) {
    const int col = blockIdx.x * 16 + (threadIdx.x & 15);
    const int b   = threadIdx.x >> 4;            // 0..31
    const int idx = b * NI + col;
    out[idx] = (g_W[idx] == g_M[col]) ? 1.0f : 0.0f;
    g_W[idx] = 0u;
    __syncthreads();
    if (threadIdx.x < 16)
        g_M[blockIdx.x * 16 + threadIdx.x] = 0u;
}

extern "C" void kernel_launch(void* const* d_in, const int* in_sizes, int n_in,
                              void* d_out, int out_size) {
    const float* x   = (const float*)d_in[0];   // [32, 16384] f32
    const int*   det = (const int*)d_in[1];     // [65536, 32] i32
    float*       out = (float*)d_out;           // [32, 16384] f32

    (void)in_sizes; (void)n_in; (void)out_size;

    cudaFuncSetAttribute(winner_kernel,
                         cudaFuncAttributeMaxDynamicSharedMemorySize,
                         SMEM_BYTES);

    // 1) Winner counting + inline membership histogram (needs M=W=0,
    //    guaranteed by the previous finalize / static zero-init).
    dim3 grid(NCHUNK, NPAIR);
    winner_kernel<<<grid, THREADS, SMEM_BYTES>>>(x, det);
    // 2) spike = (wins == memberships); resets W and M for the next call.
    finalize_kernel<<<NI / 16, 512>>>(out);
}

// round 14
// speedup vs baseline: 1.4990x; 1.0005x over previous
#include <cuda_runtime.h>

#define NI 16384          // inputs per batch row
#define ND 65536          // detectors
#define KK 32             // members per detector (== warp size)
#define BB 32             // batch
#define NCHUNK 32         // detector tiles
#define DET_PER_CTA (ND / NCHUNK)   // 2048
#define THREADS 1024
#define WARPS (THREADS / 32)        // 32
#define DET_PER_WARP (DET_PER_CTA / WARPS)  // 64
#define HALF (DET_PER_WARP / 2)     // 32: per-stream iterations
#define SMEM_BYTES (NI * 8)         // 128KB: uint2 {keyA, keyB} per input
#define NPAIR (BB / 2)              // 16

// Global scratch (allocation-free rule; zero-initialized at module load).
// spike(b,i) <=> wins(b,i) == memberships(i): each detector contributes one
// winner slot + K-1 loser slots, so stat = M - W. Duplicate ids and exact
// value ties preserved (winner = lowest max slot), matching jnp.argmax.
// rel_err 0.0 across R6-R13 with this identity.
// Invariant at kernel_launch entry: g_M == 0 and g_W == 0 (finalize resets
// both; statics start zeroed), so the launch is replay-deterministic.
__device__ unsigned g_M[NI];
__device__ unsigned g_W[BB * NI];

// Order-preserving float -> unsigned key: x >= y (as floats) iff
// key(x) >= key(y) as unsigned. Equal floats -> equal keys.
__device__ __forceinline__ unsigned f32_order_key(unsigned u) {
    return u ^ (((int)u >> 31) | 0x80000000u);
}

// One CTA = one detector tile x one batch pair. Width-2 x depth-2 pipeline:
// each warp runs TWO independent detector streams, with det ids prefetched
// TWO iterations ahead (LDG) and smem gathers ONE ahead (LDS on ids loaded
// a full iteration earlier). Every LDG->LDS and LDS->reduce edge has >=1
// iteration of slack; 4 memory chains in flight per warp.
// Membership histogram built inline: rows counted when (i & 15) == pair,
// exactly once per det row across the 16 pair-groups.
__global__ void __launch_bounds__(THREADS, 1) winner_kernel(
    const float* __restrict__ x,
    const int*   __restrict__ det)
{
    extern __shared__ uint2 xs2[];               // 128KB: {keyA, keyB}

    const int tid   = threadIdx.x;
    const int chunk = blockIdx.x;               // 0..NCHUNK-1
    const int pair  = blockIdx.y;               // 0..NPAIR-1
    const int b0    = pair * 2;

    // Prologue: precompute order keys for both rows (coalesced loads).
    const float* rowA = x + (size_t)b0 * NI;
    const float* rowB = rowA + NI;
    #pragma unroll
    for (int i = tid; i < NI; i += THREADS) {
        unsigned ka = f32_order_key(__float_as_uint(__ldg(rowA + i)));
        unsigned kb = f32_order_key(__float_as_uint(__ldg(rowB + i)));
        xs2[i] = make_uint2(ka, kb);
    }
    __syncthreads();

    const int lane = tid & 31;
    const int warp = tid >> 5;
    const unsigned lt_mask = (1u << lane) - 1u;
    unsigned* WA = g_W + (size_t)b0 * NI;
    unsigned* WB = WA + NI;

    // Warp w owns DET_PER_WARP consecutive detector rows; one row == 128B
    // == one coalesced warp load. Stream 0: rows [0,32); stream 1: [32,64).
    const int* dbase0 = det
        + ((size_t)(chunk * DET_PER_CTA + warp * DET_PER_WARP)) * KK + lane;
    const int* dbase1 = dbase0 + HALF * KK;

    // Pipeline prime: ids for iters 0 and 1 (both streams), gathers for 0.
    int   id0_c = __ldg(dbase0);
    int   id1_c = __ldg(dbase1);
    int   id0_n = __ldg(dbase0 + KK);
    int   id1_n = __ldg(dbase1 + KK);
    uint2 p0_c  = xs2[id0_c];
    uint2 p1_c  = xs2[id1_c];

    #pragma unroll 4
    for (int i = 0; i < HALF; i++) {
        // LDG two ahead (both streams).
        int id0_f = 0, id1_f = 0;
        if (i + 2 < HALF) {
            id0_f = __ldg(dbase0 + (i + 2) * KK);
            id1_f = __ldg(dbase1 + (i + 2) * KK);
        }
        // LDS one ahead, on ids loaded a full iteration ago.
        uint2 p0_n = make_uint2(0u, 0u), p1_n = make_uint2(0u, 0u);
        if (i + 1 < HALF) {
            p0_n = xs2[id0_n];
            p1_n = xs2[id1_n];
        }

        // Inline membership histogram (each det row exactly once).
        if ((i & (NPAIR - 1)) == pair) {
            atomicAdd(&g_M[id0_c], 1u);          // spread REDG
            atomicAdd(&g_M[id1_c], 1u);
        }

        unsigned m0A = __reduce_max_sync(0xffffffffu, p0_c.x);
        unsigned m0B = __reduce_max_sync(0xffffffffu, p0_c.y);
        unsigned m1A = __reduce_max_sync(0xffffffffu, p1_c.x);
        unsigned m1B = __reduce_max_sync(0xffffffffu, p1_c.y);
        unsigned b0A = __ballot_sync(0xffffffffu, p0_c.x == m0A);
        unsigned b0B = __ballot_sync(0xffffffffu, p0_c.y == m0B);
        unsigned b1A = __ballot_sync(0xffffffffu, p1_c.x == m1A);
        unsigned b1B = __ballot_sync(0xffffffffu, p1_c.y == m1B);
        // winner = lowest lane achieving max (jnp.argmax tie-break);
        // one fire-and-forget gmem RED.ADD per (detector, batch).
        if (p0_c.x == m0A && (b0A & lt_mask) == 0u) atomicAdd(WA + id0_c, 1u);
        if (p0_c.y == m0B && (b0B & lt_mask) == 0u) atomicAdd(WB + id0_c, 1u);
        if (p1_c.x == m1A && (b1A & lt_mask) == 0u) atomicAdd(WA + id1_c, 1u);
        if (p1_c.y == m1B && (b1B & lt_mask) == 0u) atomicAdd(WB + id1_c, 1u);

        id0_c = id0_n; id1_c = id1_n;
        id0_n = id0_f; id1_n = id1_f;
        p0_c  = p0_n;  p1_c  = p1_n;
    }
}

// Finalize: 1024 blocks x 512 threads; block j owns 16 columns for ALL 32
// batches (one element per thread; consecutive tids -> consecutive columns,
// coalesced). g_M[col] is read only inside its owning block, so after
// __syncthreads() the block resets it. g_W reset inline (own address).
__global__ void __launch_bounds__(512) finalize_kernel(float* __restrict__ out) {
    const int col = blockIdx.x * 16 + (threadIdx.x & 15);
    const int b   = threadIdx.x >> 4;            // 0..31
    const int idx = b * NI + col;
    out[idx] = (g_W[idx] == g_M[col]) ? 1.0f : 0.0f;
    g_W[idx] = 0u;
    __syncthreads();
    if (threadIdx.x < 16)
        g_M[blockIdx.x * 16 + threadIdx.x] = 0u;
}

extern "C" void kernel_launch(void* const* d_in, const int* in_sizes, int n_in,
                              void* d_out, int out_size) {
    const float* x   = (const float*)d_in[0];   // [32, 16384] f32
    const int*   det = (const int*)d_in[1];     // [65536, 32] i32
    float*       out = (float*)d_out;           // [32, 16384] f32

    (void)in_sizes; (void)n_in; (void)out_size;

    cudaFuncSetAttribute(winner_kernel,
                         cudaFuncAttributeMaxDynamicSharedMemorySize,
                         SMEM_BYTES);

    // 1) Winner counting + inline membership histogram (needs M=W=0,
    //    guaranteed by the previous finalize / static zero-init).
    dim3 grid(NCHUNK, NPAIR);
    winner_kernel<<<grid, THREADS, SMEM_BYTES>>>(x, det);
    // 2) spike = (wins == memberships); resets W and M for the next call.
    finalize_kernel<<<NI / 16, 512>>>(out);
}